// round 1
// baseline (speedup 1.0000x reference)
#include <cuda_runtime.h>
#include <math.h>

// ExamplarLoss: N=8192 rows (interleaved views), D=128.
// loss = (1/N) * sum_i [ logsumexp_j(S[i,:]) - S[i, i^1] ],  S = Lhat @ Lhat^T, diag := 0
// Fused GEMM + online logsumexp: never materialize S.

#define NN 8192
#define DD 128
#define BM 32
#define BN 64
#define PB 132           // B tile pitch (pad to dodge worst smem conflicts, keep float4 align)
#define NTHREADS 128
#define NTILES (NN / BN) // 128

__device__ float g_Lhat[NN * DD];  // row-normalized interleaved latent (4 MB)
__device__ float g_lse[NN];
__device__ float g_pos[NN];

// ---------------------------------------------------------------------------
// Phase 1: interleave + normalize. One block per row, 128 threads.
// Lhat[i] = L[i] / ||L[i]||  (EPS = 1.0)  =>  S = Lhat @ Lhat^T exactly.
// ---------------------------------------------------------------------------
__global__ void prep_kernel(const float* __restrict__ l1, const float* __restrict__ l2) {
    const int row = blockIdx.x;
    const float* src = (row & 1) ? l2 : l1;
    const float v = src[(row >> 1) * DD + threadIdx.x];
    float sq = v * v;
    #pragma unroll
    for (int o = 16; o; o >>= 1) sq += __shfl_xor_sync(0xffffffffu, sq, o);
    __shared__ float ws[4];
    if ((threadIdx.x & 31) == 0) ws[threadIdx.x >> 5] = sq;
    __syncthreads();
    const float total = ws[0] + ws[1] + ws[2] + ws[3];
    g_Lhat[row * DD + threadIdx.x] = v * rsqrtf(total);
}

// ---------------------------------------------------------------------------
// Phase 2: fused GEMM + online logsumexp.
// Each block owns BM=32 full rows; iterates over all 128 column tiles of 64.
// 128 threads: tx in [0,16) -> 4 cols each, ty in [0,8) -> 4 rows each.
// Per-thread running (m, s) over its column subset; shfl-merge across tx at end.
// ---------------------------------------------------------------------------
extern __shared__ float smem[];

__global__ void __launch_bounds__(NTHREADS) sim_kernel() {
    float* As = smem;               // [BM][DD]  (unpadded: reads are broadcast)
    float* Bs = smem + BM * DD;     // [BN][PB]

    const int tid = threadIdx.x;
    const int tx = tid & 15;
    const int ty = tid >> 4;
    const int rowBase = blockIdx.x * BM;
    const int r0 = rowBase + ty * 4;

    // Load A tile once (coalesced float4; 4096 floats).
    {
        const float4* src = (const float4*)(g_Lhat + rowBase * DD);
        float4* dst = (float4*)As;
        #pragma unroll
        for (int i = tid; i < BM * DD / 4; i += NTHREADS) dst[i] = src[i];
    }

    float m[4], s[4], pos[4];
    #pragma unroll
    for (int i = 0; i < 4; i++) { m[i] = -INFINITY; s[i] = 0.f; pos[i] = -INFINITY; }

    for (int jt = 0; jt < NTILES; jt++) {
        __syncthreads();
        // Load B tile [BN][DD] -> pitch PB (coalesced gmem float4, conflict-free smem writes)
        {
            const float4* src = (const float4*)(g_Lhat + jt * BN * DD);
            #pragma unroll
            for (int i = tid; i < BN * DD / 4; i += NTHREADS) {
                const int n = i >> 5;      // DD/4 = 32 chunks per row
                const int c = i & 31;
                *(float4*)(Bs + n * PB + c * 4) = src[i];
            }
        }
        __syncthreads();

        float acc[4][4];
        #pragma unroll
        for (int i = 0; i < 4; i++)
            #pragma unroll
            for (int j = 0; j < 4; j++) acc[i][j] = 0.f;

        #pragma unroll 4
        for (int kk = 0; kk < DD; kk += 4) {
            float4 a[4], b[4];
            #pragma unroll
            for (int e = 0; e < 4; e++) a[e] = *(const float4*)(As + (ty * 4 + e) * DD + kk);
            #pragma unroll
            for (int e = 0; e < 4; e++) b[e] = *(const float4*)(Bs + (tx * 4 + e) * PB + kk);
            #pragma unroll
            for (int i = 0; i < 4; i++)
                #pragma unroll
                for (int j = 0; j < 4; j++) {
                    acc[i][j] += a[i].x * b[j].x;
                    acc[i][j] += a[i].y * b[j].y;
                    acc[i][j] += a[i].z * b[j].z;
                    acc[i][j] += a[i].w * b[j].w;
                }
        }

        // Online softmax merge for this tile (diag := 0, positive pair capture).
        const int c0 = jt * BN + tx * 4;
        #pragma unroll
        for (int i = 0; i < 4; i++) {
            const int gr = r0 + i;
            float v[4];
            #pragma unroll
            for (int j = 0; j < 4; j++) {
                v[j] = acc[i][j];
                const int gc = c0 + j;
                if (gc == gr) v[j] = 0.f;
                if (gc == (gr ^ 1)) pos[i] = v[j];
            }
            const float tm = fmaxf(fmaxf(v[0], v[1]), fmaxf(v[2], v[3]));
            const float nm = fmaxf(m[i], tm);
            s[i] = s[i] * __expf(m[i] - nm)
                 + __expf(v[0] - nm) + __expf(v[1] - nm)
                 + __expf(v[2] - nm) + __expf(v[3] - nm);
            m[i] = nm;
        }
    }

    // Merge (m, s) across the 16 tx lanes (stays inside half-warps: xor 1..8).
    #pragma unroll
    for (int off = 1; off < 16; off <<= 1) {
        #pragma unroll
        for (int i = 0; i < 4; i++) {
            const float om = __shfl_xor_sync(0xffffffffu, m[i], off);
            const float os = __shfl_xor_sync(0xffffffffu, s[i], off);
            const float nm = fmaxf(m[i], om);
            s[i] = s[i] * __expf(m[i] - nm) + os * __expf(om - nm);
            m[i] = nm;
            pos[i] = fmaxf(pos[i], __shfl_xor_sync(0xffffffffu, pos[i], off));
        }
    }
    if (tx == 0) {
        #pragma unroll
        for (int i = 0; i < 4; i++) {
            g_lse[r0 + i] = m[i] + logf(s[i]);
            g_pos[r0 + i] = pos[i];
        }
    }
}

// ---------------------------------------------------------------------------
// Phase 3: final scalar reduce: loss = (1/N) * sum_i (lse_i - pos_i)
// ---------------------------------------------------------------------------
__global__ void reduce_kernel(float* __restrict__ out) {
    __shared__ float ws[8];
    const int tid = threadIdx.x;  // 256
    float acc = 0.f;
    for (int i = tid; i < NN; i += 256) acc += g_lse[i] - g_pos[i];
    #pragma unroll
    for (int o = 16; o; o >>= 1) acc += __shfl_xor_sync(0xffffffffu, acc, o);
    if ((tid & 31) == 0) ws[tid >> 5] = acc;
    __syncthreads();
    if (tid < 8) {
        acc = ws[tid];
        #pragma unroll
        for (int o = 4; o; o >>= 1) acc += __shfl_xor_sync(0x000000ffu, acc, o);
        if (tid == 0) out[0] = acc / (float)NN;
    }
}

extern "C" void kernel_launch(void* const* d_in, const int* in_sizes, int n_in,
                              void* d_out, int out_size) {
    const float* l1 = (const float*)d_in[0];
    const float* l2 = (const float*)d_in[1];
    float* out = (float*)d_out;

    const int smem_bytes = (BM * DD + BN * PB) * (int)sizeof(float);  // 50,176 B
    cudaFuncSetAttribute(sim_kernel, cudaFuncAttributeMaxDynamicSharedMemorySize, smem_bytes);

    prep_kernel<<<NN, DD>>>(l1, l2);
    sim_kernel<<<NN / BM, NTHREADS, smem_bytes>>>();
    reduce_kernel<<<1, 256>>>(out);
}

// round 3
// speedup vs baseline: 18.9858x; 18.9858x over previous
#include <cuda_runtime.h>
#include <cuda_bf16.h>
#include <math.h>
#include <stdint.h>

// ExamplarLoss fused: S = Lhat@Lhat^T via mma.sync bf16 (base sm_100 ISA),
// per-row sum of exp fused into the GEMM epilogue (no max needed: |S|<=1),
// diagonal corrected analytically, positive pair recomputed as a 128-dot.
// Trick: data pre-scaled by sqrt(log2e) so epilogue is a bare exp2f.

#define NN 8192
#define DD 128

__device__ uint4  g_bf4[NN * DD / 8];   // normalized*sqrt(log2e) rows, bf16 (2 MB)
__device__ float  g_part[4 * NN];       // per-(colchunk,row) partial sum of exp
__device__ float  g_contrib[NN];

#define SQRT_LOG2E 1.2011224087864498f
#define LN2F       0.6931471805599453f

// ------------------------- PTX helpers (base ISA) -------------------------
__device__ __forceinline__ uint32_t smem_u32(const void* p) {
    uint32_t a;
    asm("{ .reg .u64 t; cvta.to.shared.u64 t, %1; cvt.u32.u64 %0, t; }" : "=r"(a) : "l"(p));
    return a;
}
__device__ __forceinline__ void cp16(uint32_t dst, const void* src) {
    asm volatile("cp.async.cg.shared.global [%0], [%1], 16;" :: "r"(dst), "l"(src));
}
#define CP_COMMIT() asm volatile("cp.async.commit_group;" ::: "memory")
#define CP_WAIT0()  asm volatile("cp.async.wait_group 0;" ::: "memory")

__device__ __forceinline__ void ldsm4(uint32_t (&r)[4], uint32_t addr) {
    asm volatile("ldmatrix.sync.aligned.m8n8.x4.shared.b16 {%0,%1,%2,%3}, [%4];"
                 : "=r"(r[0]), "=r"(r[1]), "=r"(r[2]), "=r"(r[3]) : "r"(addr));
}
__device__ __forceinline__ void mma16816(float (&d)[4], const uint32_t (&a)[4],
                                         const uint32_t* b) {
    asm volatile("mma.sync.aligned.m16n8k16.row.col.f32.bf16.bf16.f32 "
                 "{%0,%1,%2,%3}, {%4,%5,%6,%7}, {%8,%9}, {%0,%1,%2,%3};"
                 : "+f"(d[0]), "+f"(d[1]), "+f"(d[2]), "+f"(d[3])
                 : "r"(a[0]), "r"(a[1]), "r"(a[2]), "r"(a[3]), "r"(b[0]), "r"(b[1]));
}

// ---------------- Phase 1: normalize -> bf16*sqrt(log2e) (warp/row) -------
__global__ void __launch_bounds__(256) prep_kernel(const float* __restrict__ l1,
                                                   const float* __restrict__ l2) {
    const int row = blockIdx.x * 8 + (threadIdx.x >> 5);
    const int lane = threadIdx.x & 31;
    const float* src = (row & 1) ? l2 : l1;
    const float4 v = ((const float4*)(src + (row >> 1) * DD))[lane];
    float sq = v.x * v.x + v.y * v.y + v.z * v.z + v.w * v.w;
    #pragma unroll
    for (int o = 16; o; o >>= 1) sq += __shfl_xor_sync(0xffffffffu, sq, o);
    const float inv = rsqrtf(sq) * SQRT_LOG2E;
    __nv_bfloat162 p0 = __floats2bfloat162_rn(v.x * inv, v.y * inv);
    __nv_bfloat162 p1 = __floats2bfloat162_rn(v.z * inv, v.w * inv);
    uint2 packed;
    packed.x = *(uint32_t*)&p0;
    packed.y = *(uint32_t*)&p1;
    ((uint2*)g_bf4)[row * 32 + lane] = packed;
}

// ---------------- Phase 2: HMMA GEMM + fused sum-exp2 ----------------
// SMEM: A 32KB | B0 64KB | B1 64KB | red 512B  (XOR-16B swizzle per 256B row)
#define S_A   0
#define S_B   32768
#define S_RED 163840
#define S_TOT 164352

__global__ void __launch_bounds__(256, 1) sim_kernel() {
    extern __shared__ char sm[];
    const uint32_t sb = smem_u32(sm);
    const int tid = threadIdx.x;
    const int w = tid >> 5, l = tid & 31;
    const int rw = w >> 2, cw = w & 3;          // warp: 64-row group x 64-col group
    const int rb = blockIdx.x >> 2;             // 128-row block
    const int cc = blockIdx.x & 3;              // 2048-col chunk

    float* red = (float*)(sm + S_RED);
    if (tid < 128) red[tid] = 0.f;

    const char* gbase = (const char*)g_bf4;

    // A tile 128x128 (2048 16B chunks) + B tile 0 (4096 chunks), swizzled stores
    {
        const char* gA = gbase + (size_t)rb * 128 * 256;
        #pragma unroll
        for (int j = 0; j < 8; j++) {
            const int idx = j * 256 + tid, r = idx >> 4, c = idx & 15;
            cp16(sb + S_A + r * 256 + ((c ^ (r & 7)) << 4), gA + idx * 16);
        }
        const char* gB = gbase + (size_t)(cc * 2048) * 256;
        #pragma unroll
        for (int j = 0; j < 16; j++) {
            const int idx = j * 256 + tid, n = idx >> 4, c = idx & 15;
            cp16(sb + S_B + n * 256 + ((c ^ (n & 7)) << 4), gB + idx * 16);
        }
    }
    CP_COMMIT();
    CP_WAIT0();
    __syncthreads();

    // per-thread ldmatrix base addresses
    uint32_t aBase[4], bOff[4];
    {
        const int axor_row = l & 15;
        #pragma unroll
        for (int mf = 0; mf < 4; mf++)
            aBase[mf] = sb + S_A + (rw * 64 + mf * 16 + axor_row) * 256;
        const int bn = (l & 7) + ((l >> 4) << 3);
        #pragma unroll
        for (int nf2 = 0; nf2 < 4; nf2++)
            bOff[nf2] = (uint32_t)((cw * 64 + nf2 * 16 + bn) * 256);
    }
    const int akc = l >> 4;          // A k-chunk select
    const int bkc = (l >> 3) & 1;    // B k-chunk select
    const int sxor = l & 7;          // swizzle phase (row&7 for both A and B lanes)

    float part[8];
    #pragma unroll
    for (int p = 0; p < 8; p++) part[p] = 0.f;

    for (int jt = 0; jt < 8; jt++) {
        if (jt < 7) {  // prefetch next B tile into the other buffer
            const uint32_t bufw = sb + S_B + (uint32_t)(((jt + 1) & 1) * 65536);
            const char* gB = gbase + (size_t)(cc * 2048 + (jt + 1) * 256) * 256;
            #pragma unroll
            for (int j = 0; j < 16; j++) {
                const int idx = j * 256 + tid, n = idx >> 4, c = idx & 15;
                cp16(bufw + n * 256 + ((c ^ (n & 7)) << 4), gB + idx * 16);
            }
            CP_COMMIT();
        }

        const uint32_t bb = sb + S_B + (uint32_t)((jt & 1) * 65536);
        float acc[4][8][4];
        #pragma unroll
        for (int mf = 0; mf < 4; mf++)
            #pragma unroll
            for (int nf = 0; nf < 8; nf++)
                #pragma unroll
                for (int e = 0; e < 4; e++) acc[mf][nf][e] = 0.f;

        #pragma unroll
        for (int k = 0; k < 8; k++) {
            uint32_t a[4][4], b[4][4];  // b[nf2] holds 2 n8-group frags
            #pragma unroll
            for (int mf = 0; mf < 4; mf++)
                ldsm4(a[mf], aBase[mf] + (((k * 2 + akc) ^ sxor) << 4));
            #pragma unroll
            for (int nf2 = 0; nf2 < 4; nf2++)
                ldsm4(b[nf2], bb + bOff[nf2] + (((k * 2 + bkc) ^ sxor) << 4));
            #pragma unroll
            for (int mf = 0; mf < 4; mf++)
                #pragma unroll
                for (int nf = 0; nf < 8; nf++)
                    mma16816(acc[mf][nf], a[mf], &b[nf >> 1][(nf & 1) * 2]);
        }

        // fused epilogue: sum of exp2 per output row
        #pragma unroll
        for (int mf = 0; mf < 4; mf++)
            #pragma unroll
            for (int nf = 0; nf < 8; nf++) {
                part[mf * 2 + 0] += exp2f(acc[mf][nf][0]) + exp2f(acc[mf][nf][1]);
                part[mf * 2 + 1] += exp2f(acc[mf][nf][2]) + exp2f(acc[mf][nf][3]);
            }

        if (jt < 7) CP_WAIT0();
        __syncthreads();
    }

    // reduce across the quad (lanes sharing an output row), then across warps
    #pragma unroll
    for (int p = 0; p < 8; p++) {
        part[p] += __shfl_xor_sync(0xffffffffu, part[p], 1);
        part[p] += __shfl_xor_sync(0xffffffffu, part[p], 2);
    }
    if ((l & 3) == 0) {
        #pragma unroll
        for (int p = 0; p < 8; p++) {
            const int row = rw * 64 + (p >> 1) * 16 + (l >> 2) + (p & 1) * 8;
            atomicAdd(&red[row], part[p]);
        }
    }
    __syncthreads();
    if (tid < 128) g_part[cc * NN + rb * 128 + tid] = red[tid];
}

// ---------------- Phase 3: per-row contrib = lse - pos ----------------
__global__ void __launch_bounds__(256) finrow_kernel() {
    const int i = blockIdx.x * 256 + threadIdx.x;
    const float s = g_part[i] + g_part[NN + i] + g_part[2 * NN + i] + g_part[3 * NN + i];
    const __nv_bfloat162* a = (const __nv_bfloat162*)g_bf4 + (size_t)i * 64;
    const __nv_bfloat162* b = (const __nv_bfloat162*)g_bf4 + (size_t)(i ^ 1) * 64;
    float sii = 0.f, pos = 0.f;
    #pragma unroll
    for (int k = 0; k < 64; k++) {
        const float2 av = __bfloat1622float2(a[k]);
        const float2 bv = __bfloat1622float2(b[k]);
        sii += av.x * av.x + av.y * av.y;
        pos += av.x * bv.x + av.y * bv.y;
    }
    // s includes exp2(S'_ii); reference zeroes the diagonal -> contribution exp(0)=1
    g_contrib[i] = logf(s + 1.f - exp2f(sii)) - pos * LN2F;
}

// ---------------- Phase 4: scalar reduce ----------------
__global__ void __launch_bounds__(256) reduce_kernel(float* __restrict__ out) {
    __shared__ float ws[8];
    const int tid = threadIdx.x;
    float acc = 0.f;
    for (int i = tid; i < NN; i += 256) acc += g_contrib[i];
    #pragma unroll
    for (int o = 16; o; o >>= 1) acc += __shfl_xor_sync(0xffffffffu, acc, o);
    if ((tid & 31) == 0) ws[tid >> 5] = acc;
    __syncthreads();
    if (tid < 8) {
        acc = ws[tid];
        #pragma unroll
        for (int o = 4; o; o >>= 1) acc += __shfl_xor_sync(0x000000ffu, acc, o);
        if (tid == 0) out[0] = acc / (float)NN;
    }
}

extern "C" void kernel_launch(void* const* d_in, const int* in_sizes, int n_in,
                              void* d_out, int out_size) {
    const float* l1 = (const float*)d_in[0];
    const float* l2 = (const float*)d_in[1];
    float* out = (float*)d_out;

    cudaFuncSetAttribute(sim_kernel, cudaFuncAttributeMaxDynamicSharedMemorySize, S_TOT);

    prep_kernel<<<NN / 8, 256>>>(l1, l2);
    sim_kernel<<<256, 256, S_TOT>>>();
    finrow_kernel<<<NN / 256, 256>>>();
    reduce_kernel<<<1, 256>>>(out);
}

// round 4
// speedup vs baseline: 26.8056x; 1.4119x over previous
#include <cuda_runtime.h>
#include <cuda_bf16.h>
#include <math.h>
#include <stdint.h>

// ExamplarLoss fused, symmetric: S = Lhat@Lhat^T computed only on upper-tri
// 128x128 tiles; each off-diag tile contributes exp(S_ij) to row i (row sums)
// AND row j (col sums). |S|<=1 -> max-free sum of exp2 (data pre-scaled by
// sqrt(log2e)). Diagonal + positive-pair handled analytically in finrow.

#define NN 8192
#define DD 128
#define NB 64            // 64 row-blocks of 128

__device__ uint4  g_bf4[NN * DD / 8];   // normalized*sqrt(log2e) rows, bf16 (2 MB)
__device__ float  g_rowsum[NN];         // per-row sum of exp2 (atomic accum)

#define SQRT_LOG2E 1.2011224087864498f
#define LN2F       0.6931471805599453f

// ------------------------- PTX helpers (base ISA) -------------------------
__device__ __forceinline__ uint32_t smem_u32(const void* p) {
    uint32_t a;
    asm("{ .reg .u64 t; cvta.to.shared.u64 t, %1; cvt.u32.u64 %0, t; }" : "=r"(a) : "l"(p));
    return a;
}
__device__ __forceinline__ void cp16(uint32_t dst, const void* src) {
    asm volatile("cp.async.cg.shared.global [%0], [%1], 16;" :: "r"(dst), "l"(src));
}
#define CP_COMMIT() asm volatile("cp.async.commit_group;" ::: "memory")
#define CP_WAIT0()  asm volatile("cp.async.wait_group 0;" ::: "memory")

__device__ __forceinline__ void ldsm4(uint32_t (&r)[4], uint32_t addr) {
    asm volatile("ldmatrix.sync.aligned.m8n8.x4.shared.b16 {%0,%1,%2,%3}, [%4];"
                 : "=r"(r[0]), "=r"(r[1]), "=r"(r[2]), "=r"(r[3]) : "r"(addr));
}
__device__ __forceinline__ void mma16816(float (&d)[4], const uint32_t (&a)[4],
                                         const uint32_t* b) {
    asm volatile("mma.sync.aligned.m16n8k16.row.col.f32.bf16.bf16.f32 "
                 "{%0,%1,%2,%3}, {%4,%5,%6,%7}, {%8,%9}, {%0,%1,%2,%3};"
                 : "+f"(d[0]), "+f"(d[1]), "+f"(d[2]), "+f"(d[3])
                 : "r"(a[0]), "r"(a[1]), "r"(a[2]), "r"(a[3]), "r"(b[0]), "r"(b[1]));
}

// ---------------- Phase 1: normalize -> bf16*sqrt(log2e); zero accumulators
__global__ void __launch_bounds__(256) prep_kernel(const float* __restrict__ l1,
                                                   const float* __restrict__ l2,
                                                   float* __restrict__ out) {
    const int row = blockIdx.x * 8 + (threadIdx.x >> 5);
    const int lane = threadIdx.x & 31;
    // zero g_rowsum (8 per block) and out
    if (threadIdx.x < 8) g_rowsum[blockIdx.x * 8 + threadIdx.x] = 0.f;
    if (blockIdx.x == 0 && threadIdx.x == 0) out[0] = 0.f;

    const float* src = (row & 1) ? l2 : l1;
    const float4 v = ((const float4*)(src + (row >> 1) * DD))[lane];
    float sq = v.x * v.x + v.y * v.y + v.z * v.z + v.w * v.w;
    #pragma unroll
    for (int o = 16; o; o >>= 1) sq += __shfl_xor_sync(0xffffffffu, sq, o);
    const float inv = rsqrtf(sq) * SQRT_LOG2E;
    __nv_bfloat162 p0 = __floats2bfloat162_rn(v.x * inv, v.y * inv);
    __nv_bfloat162 p1 = __floats2bfloat162_rn(v.z * inv, v.w * inv);
    uint2 packed;
    packed.x = *(uint32_t*)&p0;
    packed.y = *(uint32_t*)&p1;
    ((uint2*)g_bf4)[row * 32 + lane] = packed;
}

// ---------------- Phase 2: symmetric HMMA GEMM + fused dual-sided sum-exp2
// SMEM: A 32KB | B 32KB | red_row 512B | red_col 512B
#define S_A    0
#define S_B    32768
#define S_RR   65536
#define S_RC   66048
#define S_TOT  66560

__global__ void __launch_bounds__(256, 2) sim_kernel() {
    extern __shared__ char sm[];
    const uint32_t sb = smem_u32(sm);
    const int tid = threadIdx.x;
    const int w = tid >> 5, l = tid & 31;
    const int rw = w >> 1, cw = w & 1;      // 4 row-groups of 32, 2 col-groups of 64

    // decode upper-triangular (ib <= jb) tile index
    const int t = blockIdx.x;
    int ib = (int)floorf((2.f * NB + 1.f -
              sqrtf((2.f * NB + 1.f) * (2.f * NB + 1.f) - 8.f * (float)t)) * 0.5f);
    if (ib < 0) ib = 0;
    if (ib > NB - 1) ib = NB - 1;
    #pragma unroll 1
    while (ib > 0 && ib * NB - (ib * (ib - 1)) / 2 > t) ib--;
    #pragma unroll 1
    while (ib < NB - 1 && (ib + 1) * NB - ((ib + 1) * ib) / 2 <= t) ib++;
    const int jb = ib + (t - (ib * NB - (ib * (ib - 1)) / 2));
    const bool diag = (ib == jb);

    float* red_row = (float*)(sm + S_RR);
    float* red_col = (float*)(sm + S_RC);
    if (tid < 128) { red_row[tid] = 0.f; red_col[tid] = 0.f; }

    // load A (rows of block ib) and B (rows of block jb), swizzled
    {
        const char* gA = (const char*)g_bf4 + (size_t)ib * 128 * 256;
        const char* gB = (const char*)g_bf4 + (size_t)jb * 128 * 256;
        #pragma unroll
        for (int jj = 0; jj < 8; jj++) {
            const int idx = jj * 256 + tid, r = idx >> 4, c = idx & 15;
            const uint32_t off = (uint32_t)(r * 256 + ((c ^ (r & 7)) << 4));
            cp16(sb + S_A + off, gA + idx * 16);
            cp16(sb + S_B + off, gB + idx * 16);
        }
    }
    CP_COMMIT();
    CP_WAIT0();
    __syncthreads();

    // ldmatrix addresses
    uint32_t aBase[2], bOff[4];
    #pragma unroll
    for (int mf = 0; mf < 2; mf++)
        aBase[mf] = sb + S_A + (uint32_t)((rw * 32 + mf * 16 + (l & 15)) * 256);
    const int bn = (l & 7) + ((l >> 4) << 3);
    #pragma unroll
    for (int nf2 = 0; nf2 < 4; nf2++)
        bOff[nf2] = sb + S_B + (uint32_t)((cw * 64 + nf2 * 16 + bn) * 256);
    const int akc = l >> 4;
    const int bkc = (l >> 3) & 1;
    const int sxor = l & 7;

    float acc[2][8][4];
    #pragma unroll
    for (int mf = 0; mf < 2; mf++)
        #pragma unroll
        for (int nf = 0; nf < 8; nf++)
            #pragma unroll
            for (int e = 0; e < 4; e++) acc[mf][nf][e] = 0.f;

    #pragma unroll
    for (int k = 0; k < 8; k++) {
        uint32_t a[2][4], b[4][4];
        #pragma unroll
        for (int mf = 0; mf < 2; mf++)
            ldsm4(a[mf], aBase[mf] + (((k * 2 + akc) ^ sxor) << 4));
        #pragma unroll
        for (int nf2 = 0; nf2 < 4; nf2++)
            ldsm4(b[nf2], bOff[nf2] + (((k * 2 + bkc) ^ sxor) << 4));
        #pragma unroll
        for (int mf = 0; mf < 2; mf++)
            #pragma unroll
            for (int nf = 0; nf < 8; nf++)
                mma16816(acc[mf][nf], a[mf], &b[nf >> 1][(nf & 1) * 2]);
    }

    // epilogue: exp2 once per element; accumulate row partials and col partials
    float rpart[2][2] = {{0.f, 0.f}, {0.f, 0.f}};   // [mf][half]
    float cpart[8][2];                              // [nf][e&1]
    #pragma unroll
    for (int nf = 0; nf < 8; nf++) { cpart[nf][0] = 0.f; cpart[nf][1] = 0.f; }

    #pragma unroll
    for (int mf = 0; mf < 2; mf++)
        #pragma unroll
        for (int nf = 0; nf < 8; nf++) {
            const float e0 = exp2f(acc[mf][nf][0]);
            const float e1 = exp2f(acc[mf][nf][1]);
            const float e2 = exp2f(acc[mf][nf][2]);
            const float e3 = exp2f(acc[mf][nf][3]);
            rpart[mf][0] += e0 + e1;
            rpart[mf][1] += e2 + e3;
            cpart[nf][0] += e0 + e2;
            cpart[nf][1] += e1 + e3;
        }

    // row sums: reduce across quad lanes (l&3)
    #pragma unroll
    for (int off = 1; off <= 2; off <<= 1)
        #pragma unroll
        for (int mf = 0; mf < 2; mf++)
            #pragma unroll
            for (int h = 0; h < 2; h++)
                rpart[mf][h] += __shfl_xor_sync(0xffffffffu, rpart[mf][h], off);
    if ((l & 3) == 0) {
        #pragma unroll
        for (int mf = 0; mf < 2; mf++)
            #pragma unroll
            for (int h = 0; h < 2; h++)
                atomicAdd(&red_row[rw * 32 + mf * 16 + h * 8 + (l >> 2)], rpart[mf][h]);
    }

    // col sums: reduce across row lanes (l>>2), only needed off-diagonal
    if (!diag) {
        #pragma unroll
        for (int off = 4; off <= 16; off <<= 1)
            #pragma unroll
            for (int nf = 0; nf < 8; nf++)
                #pragma unroll
                for (int p = 0; p < 2; p++)
                    cpart[nf][p] += __shfl_xor_sync(0xffffffffu, cpart[nf][p], off);
        if (l < 4) {
            #pragma unroll
            for (int nf = 0; nf < 8; nf++)
                #pragma unroll
                for (int p = 0; p < 2; p++)
                    atomicAdd(&red_col[cw * 64 + nf * 8 + l * 2 + p], cpart[nf][p]);
        }
    }
    __syncthreads();

    if (tid < 128) {
        atomicAdd(&g_rowsum[ib * 128 + tid], red_row[tid]);
        if (!diag) atomicAdd(&g_rowsum[jb * 128 + tid], red_col[tid]);
    }
}

// ---------------- Phase 3: per-row contrib, block-reduce, atomic into out --
__global__ void __launch_bounds__(256) finrow_kernel(float* __restrict__ out) {
    __shared__ float ws[8];
    const int i = blockIdx.x * 256 + threadIdx.x;
    const float s = g_rowsum[i];
    const __nv_bfloat162* a = (const __nv_bfloat162*)g_bf4 + (size_t)i * 64;
    const __nv_bfloat162* b = (const __nv_bfloat162*)g_bf4 + (size_t)(i ^ 1) * 64;
    float sii = 0.f, pos = 0.f;
    #pragma unroll
    for (int k = 0; k < 64; k++) {
        const float2 av = __bfloat1622float2(a[k]);
        const float2 bv = __bfloat1622float2(b[k]);
        sii += av.x * av.x + av.y * av.y;
        pos += av.x * bv.x + av.y * bv.y;
    }
    // s includes exp2(S'_ii); reference zeroes the diagonal -> contribution exp(0)=1
    float contrib = logf(s + 1.f - exp2f(sii)) - pos * LN2F;

    #pragma unroll
    for (int o = 16; o; o >>= 1) contrib += __shfl_xor_sync(0xffffffffu, contrib, o);
    if ((threadIdx.x & 31) == 0) ws[threadIdx.x >> 5] = contrib;
    __syncthreads();
    if (threadIdx.x < 8) {
        float acc = ws[threadIdx.x];
        #pragma unroll
        for (int o = 4; o; o >>= 1) acc += __shfl_xor_sync(0x000000ffu, acc, o);
        if (threadIdx.x == 0) atomicAdd(out, acc * (1.f / (float)NN));
    }
}

extern "C" void kernel_launch(void* const* d_in, const int* in_sizes, int n_in,
                              void* d_out, int out_size) {
    const float* l1 = (const float*)d_in[0];
    const float* l2 = (const float*)d_in[1];
    float* out = (float*)d_out;

    cudaFuncSetAttribute(sim_kernel, cudaFuncAttributeMaxDynamicSharedMemorySize, S_TOT);

    prep_kernel<<<NN / 8, 256>>>(l1, l2, out);
    sim_kernel<<<NB * (NB + 1) / 2, 256, S_TOT>>>();
    finrow_kernel<<<NN / 256, 256>>>(out);
}